// round 10
// baseline (speedup 1.0000x reference)
#include <cuda_runtime.h>
#include <cstdint>

#define N_NODES 100000
#define N_EDGES 1000000
#define F 64
#define G 128
#define CHUNK 98   // ceil(N_NODES / 1024)

// ---------------- scratch (static device globals; no allocation) ----------
__device__ __align__(16) float d_XR[(size_t)N_NODES * F];  // x @ w1_rel.T
__device__ __align__(16) float d_H [(size_t)N_NODES * F];  // x @ w1_root.T + b1
__device__ float d_a [N_NODES];
__device__ float d_S [N_NODES];
__device__ __align__(8) float d_vrel[F];
__device__ __align__(8) float d_vroot[F];
__device__ float d_c2;
__device__ float d_gsum[G];
__device__ float d_gcnt[G];
// CSR by dst
__device__ int   d_deg[N_NODES];
__device__ int   d_off[N_NODES];
__device__ int   d_cursor[N_NODES];
__device__ __align__(8) int2 d_ep[N_EDGES];   // {src, __float_as_int(w)}

// ------- init (block 0) + zero degree histogram (all blocks) --------------
__global__ __launch_bounds__(256)
void k_init_zero(const float* __restrict__ w2rel,
                 const float* __restrict__ w2root,
                 const float* __restrict__ b2,
                 const float* __restrict__ wlin) {
    int tid = threadIdx.x;
    if (blockIdx.x == 0) {
        if (tid < G) { d_gsum[tid] = 0.f; d_gcnt[tid] = 0.f; }
        if (tid < F) {
            float vr = 0.f, vo = 0.f;
            #pragma unroll 8
            for (int h = 0; h < F; h++) {
                float wl = wlin[h];
                vr += wl * w2rel[h * F + tid];
                vo += wl * w2root[h * F + tid];
            }
            d_vrel[tid] = vr; d_vroot[tid] = vo;
        }
        if (tid == 0) {
            float c = 0.f;
            for (int h = 0; h < F; h++) c += wlin[h] * b2[h];
            d_c2 = c;
        }
    }
    int n = blockIdx.x * 256 + tid;
    if (n < N_NODES) d_deg[n] = 0;
}

// ---- dual GEMM (f32x2 outer product) + inlined degree count prologue -----
#define XPAD 68
#define WTPAD 132
#define SM_X_OFF 0
#define SM_WT_OFF (128 * XPAD)
#define SMEM_FLOATS (128 * XPAD + 64 * WTPAD)
#define GEMM_GRID 296

__global__ __launch_bounds__(256, 2)
void k_gemm(const float* __restrict__ x, const float* __restrict__ w1rel,
            const float* __restrict__ w1root, const float* __restrict__ b1,
            const int* __restrict__ ei) {
    extern __shared__ float sm[];
    float* sX  = sm + SM_X_OFF;    // [128][XPAD]
    float* sWt = sm + SM_WT_OFF;   // [64][WTPAD]

    int tid = threadIdx.x;

    // --- degree-count prologue: fire-and-forget RED atomics (hidden work) --
    {
        int gtid = blockIdx.x * 256 + tid;
        for (int e = gtid; e < N_EDGES; e += GEMM_GRID * 256)
            atomicAdd(&d_deg[ei[N_EDGES + e]], 1);
    }

    for (int idx = tid; idx < 128 * 64; idx += 256) {
        int o = idx >> 6, k = idx & 63;
        float v = (o < 64) ? w1rel[o * 64 + k] : w1root[(o - 64) * 64 + k];
        sWt[k * WTPAD + o] = v;
    }

    int tr = tid >> 4;
    int tc = tid & 15;
    int n0 = tr * 8;
    int o0 = tc * 8;
    float bb[8];
    #pragma unroll
    for (int q = 0; q < 8; q++) bb[q] = (tc >= 8) ? b1[o0 - 64 + q] : 0.f;

    const int ntiles = (N_NODES + 127) / 128;   // 782
    for (int tile = blockIdx.x; tile < ntiles; tile += gridDim.x) {
        int nbase  = tile * 128;
        int nvalid = min(128, N_NODES - nbase);
        __syncthreads();
        const float4* xg = reinterpret_cast<const float4*>(x + (size_t)nbase * F);
        #pragma unroll
        for (int i = 0; i < 8; i++) {
            int idx = tid + i * 256;
            int row = idx >> 4, c4 = idx & 15;
            float4 v = make_float4(0.f, 0.f, 0.f, 0.f);
            if (row < nvalid) v = xg[idx];
            *reinterpret_cast<float4*>(&sX[row * XPAD + c4 * 4]) = v;
        }
        __syncthreads();

        unsigned long long acc[8][4];
        #pragma unroll
        for (int n = 0; n < 8; n++)
            #pragma unroll
            for (int p = 0; p < 4; p++) acc[n][p] = 0ull;

        #pragma unroll 4
        for (int kk = 0; kk < 64; kk += 4) {
            unsigned long long b[4][4];
            #pragma unroll
            for (int j = 0; j < 4; j++) {
                ulonglong2 t0 = *reinterpret_cast<const ulonglong2*>(&sWt[(kk + j) * WTPAD + o0]);
                ulonglong2 t1 = *reinterpret_cast<const ulonglong2*>(&sWt[(kk + j) * WTPAD + o0 + 4]);
                b[j][0] = t0.x; b[j][1] = t0.y; b[j][2] = t1.x; b[j][3] = t1.y;
            }
            #pragma unroll
            for (int n = 0; n < 8; n++) {
                float4 av = *reinterpret_cast<const float4*>(&sX[(n0 + n) * XPAD + kk]);
                float as[4] = {av.x, av.y, av.z, av.w};
                #pragma unroll
                for (int j = 0; j < 4; j++) {
                    unsigned long long a2;
                    asm("mov.b64 %0, {%1, %1};" : "=l"(a2) : "f"(as[j]));
                    #pragma unroll
                    for (int p = 0; p < 4; p++)
                        asm("fma.rn.f32x2 %0, %1, %2, %3;"
                            : "=l"(acc[n][p])
                            : "l"(a2), "l"(b[j][p]), "l"(acc[n][p]));
                }
            }
        }

        #pragma unroll
        for (int n = 0; n < 8; n++) {
            int node = n0 + n;
            if (node >= nvalid) break;
            float o_[8];
            #pragma unroll
            for (int p = 0; p < 4; p++) {
                o_[2*p]   = __uint_as_float((unsigned)(acc[n][p] & 0xffffffffu));
                o_[2*p+1] = __uint_as_float((unsigned)(acc[n][p] >> 32));
            }
            size_t gbase = (size_t)(nbase + node) * F;
            if (tc < 8) {
                *reinterpret_cast<float4*>(&d_XR[gbase + o0]) =
                    make_float4(o_[0], o_[1], o_[2], o_[3]);
                *reinterpret_cast<float4*>(&d_XR[gbase + o0 + 4]) =
                    make_float4(o_[4], o_[5], o_[6], o_[7]);
            } else {
                *reinterpret_cast<float4*>(&d_H[gbase + o0 - 64]) =
                    make_float4(o_[0] + bb[0], o_[1] + bb[1], o_[2] + bb[2], o_[3] + bb[3]);
                *reinterpret_cast<float4*>(&d_H[gbase + o0 - 60]) =
                    make_float4(o_[4] + bb[4], o_[5] + bb[5], o_[6] + bb[6], o_[7] + bb[7]);
            }
        }
    }
}

// ---- fused exclusive scan: one block, 1024 threads, 98-node chunks -------
__global__ __launch_bounds__(1024)
void k_scan() {
    __shared__ int wsum[32];
    int tid = threadIdx.x;
    int beg = tid * CHUNK;
    int end = min(beg + CHUNK, N_NODES);
    int s = 0;
    for (int n = beg; n < end; n++) s += d_deg[n];

    int lane = tid & 31, wid = tid >> 5;
    int v = s;
    #pragma unroll
    for (int o = 1; o < 32; o <<= 1) {
        int t = __shfl_up_sync(0xffffffffu, v, o);
        if (lane >= o) v += t;
    }                                   // inclusive within warp
    if (lane == 31) wsum[wid] = v;
    __syncthreads();
    if (wid == 0) {
        int wv = wsum[lane];
        #pragma unroll
        for (int o = 1; o < 32; o <<= 1) {
            int t = __shfl_up_sync(0xffffffffu, wv, o);
            if (lane >= o) wv += t;
        }
        wsum[lane] = wv;                // inclusive warp totals
    }
    __syncthreads();
    int run = v - s + (wid > 0 ? wsum[wid - 1] : 0);   // thread-exclusive base
    for (int n = beg; n < end; n++) {
        int d = d_deg[n];
        d_off[n] = run;
        d_cursor[n] = run;
        run += d;
    }
}

__global__ __launch_bounds__(256)
void k_fill(const int* __restrict__ ei, const float* __restrict__ ew) {
    int e = blockIdx.x * blockDim.x + threadIdx.x;
    if (e >= N_EDGES) return;
    int src = ei[e];
    int dst = ei[N_EDGES + e];
    int slot = atomicAdd(&d_cursor[dst], 1);
    d_ep[slot] = make_int2(src, __float_as_int(ew[e]));
}

// ---- aggr: warp/node, fully-predicated unroll-8 gather (max MLP) ---------
__global__ __launch_bounds__(256)
void k_aggr() {
    int node = (blockIdx.x * blockDim.x + threadIdx.x) >> 5;
    int l    = threadIdx.x & 31;
    if (node >= N_NODES) return;
    int beg = d_off[node];
    int end = beg + d_deg[node];
    float a0 = 0.f, a1 = 0.f;
    const float2* XR2 = reinterpret_cast<const float2*>(d_XR);
    for (int j = beg; j < end; j += 8) {
        int2 e[8];
        #pragma unroll
        for (int q = 0; q < 8; q++)
            e[q] = (j + q < end) ? d_ep[j + q] : make_int2(0, 0);
        float2 v[8];
        #pragma unroll
        for (int q = 0; q < 8; q++)
            v[q] = (j + q < end) ? XR2[(size_t)e[q].x * 32 + l]
                                 : make_float2(0.f, 0.f);
        #pragma unroll
        for (int q = 0; q < 8; q++) {
            float w = __int_as_float(e[q].y);
            a0 = fmaf(w, v[q].x, a0);
            a1 = fmaf(w, v[q].y, a1);
        }
    }
    float2 hh = reinterpret_cast<const float2*>(d_H)[(size_t)node * 32 + l];
    float h0 = fmaxf(hh.x + a0, 0.f);
    float h1 = fmaxf(hh.y + a1, 0.f);
    float2 vr = reinterpret_cast<const float2*>(d_vrel)[l];
    float2 vo = reinterpret_cast<const float2*>(d_vroot)[l];
    float pa = h0 * vr.x + h1 * vr.y;
    float ps = h0 * vo.x + h1 * vo.y;
    #pragma unroll
    for (int o = 16; o; o >>= 1) {
        pa += __shfl_xor_sync(0xffffffffu, pa, o);
        ps += __shfl_xor_sync(0xffffffffu, ps, o);
    }
    if (l == 0) { d_a[node] = pa; d_S[node] = ps + d_c2; }
}

// ---- layer2 scalar aggregation (predicated unroll-8) + pool bins ---------
__global__ __launch_bounds__(256)
void k_scalar_pool(const int* __restrict__ batch) {
    __shared__ float sb[G];
    __shared__ float sc[G];
    int tid = threadIdx.x;
    if (tid < G) { sb[tid] = 0.f; sc[tid] = 0.f; }
    __syncthreads();
    int n = blockIdx.x * blockDim.x + tid;
    if (n < N_NODES) {
        int beg = d_off[n];
        int end = beg + d_deg[n];
        float s = 0.f;
        for (int j = beg; j < end; j += 8) {
            int2 e[8];
            #pragma unroll
            for (int q = 0; q < 8; q++)
                e[q] = (j + q < end) ? d_ep[j + q] : make_int2(0, 0);
            float v[8];
            #pragma unroll
            for (int q = 0; q < 8; q++)
                v[q] = (j + q < end) ? d_a[e[q].x] : 0.f;
            #pragma unroll
            for (int q = 0; q < 8; q++)
                s = fmaf(__int_as_float(e[q].y), v[q], s);
        }
        float S = d_S[n] + s;
        int b = batch[n];
        atomicAdd(&sb[b], S);
        atomicAdd(&sc[b], 1.0f);
    }
    __syncthreads();
    if (tid < G && (sb[tid] != 0.f || sc[tid] != 0.f)) {
        atomicAdd(&d_gsum[tid], sb[tid]);
        atomicAdd(&d_gcnt[tid], sc[tid]);
    }
}

// ---------------- final ----------------------------------------------------
__global__ void k_final(const float* __restrict__ blin, float* __restrict__ out) {
    int g = threadIdx.x;
    if (g < G) out[g] = d_gsum[g] / fmaxf(d_gcnt[g], 1.0f) + blin[0];
}

// ---------------- launch ---------------------------------------------------
extern "C" void kernel_launch(void* const* d_in, const int* in_sizes, int n_in,
                              void* d_out, int out_size) {
    const float* x     = (const float*)d_in[0];
    const int*   ei    = (const int*)d_in[1];      // int32 (JAX x64 disabled)
    const float* ew    = (const float*)d_in[2];
    const int*   batch = (const int*)d_in[3];
    const float* w1rel = (const float*)d_in[4];
    const float* b1rel = (const float*)d_in[5];
    const float* w1rt  = (const float*)d_in[6];
    const float* w2rel = (const float*)d_in[7];
    const float* b2rel = (const float*)d_in[8];
    const float* w2rt  = (const float*)d_in[9];
    const float* wlin  = (const float*)d_in[10];
    const float* blin  = (const float*)d_in[11];
    float* out = (float*)d_out;

    cudaFuncSetAttribute(k_gemm, cudaFuncAttributeMaxDynamicSharedMemorySize,
                         SMEM_FLOATS * 4);

    k_init_zero<<<(N_NODES + 255) / 256, 256>>>(w2rel, w2rt, b2rel, wlin);
    k_gemm<<<GEMM_GRID, 256, SMEM_FLOATS * 4>>>(x, w1rel, w1rt, b1rel, ei);
    k_scan<<<1, 1024>>>();
    k_fill<<<(N_EDGES + 255) / 256, 256>>>(ei, ew);
    k_aggr<<<(N_NODES * 32 + 255) / 256, 256>>>();
    k_scalar_pool<<<(N_NODES + 255) / 256, 256>>>(batch);
    k_final<<<1, 128>>>(blin, out);
}

// round 11
// speedup vs baseline: 1.0407x; 1.0407x over previous
#include <cuda_runtime.h>
#include <cstdint>

#define N_NODES 100000
#define N_EDGES 1000000
#define F 64
#define G 128
#define CHUNK 98   // ceil(N_NODES / 1024)

// ---------------- scratch (static device globals; no allocation) ----------
__device__ __align__(16) float d_XR[(size_t)N_NODES * F];  // x @ w1_rel.T
__device__ __align__(16) float d_H [(size_t)N_NODES * F];  // x @ w1_root.T + b1
__device__ float d_a [N_NODES];
__device__ float d_S [N_NODES];
__device__ __align__(8) float d_vrel[F];
__device__ __align__(8) float d_vroot[F];
__device__ float d_c2;
__device__ float d_gsum[G];
__device__ float d_gcnt[G];
// CSR by dst
__device__ int   d_deg[N_NODES];
__device__ int   d_off[N_NODES];
__device__ int   d_cursor[N_NODES];
__device__ __align__(8) int2 d_ep[N_EDGES];   // {src, __float_as_int(w)}

// ------- init (block 0) + zero degree histogram (all blocks) --------------
__global__ __launch_bounds__(256)
void k_init_zero(const float* __restrict__ w2rel,
                 const float* __restrict__ w2root,
                 const float* __restrict__ b2,
                 const float* __restrict__ wlin) {
    int tid = threadIdx.x;
    if (blockIdx.x == 0) {
        if (tid < G) { d_gsum[tid] = 0.f; d_gcnt[tid] = 0.f; }
        if (tid < F) {
            float vr = 0.f, vo = 0.f;
            #pragma unroll 8
            for (int h = 0; h < F; h++) {
                float wl = wlin[h];
                vr += wl * w2rel[h * F + tid];
                vo += wl * w2root[h * F + tid];
            }
            d_vrel[tid] = vr; d_vroot[tid] = vo;
        }
        if (tid == 0) {
            float c = 0.f;
            for (int h = 0; h < F; h++) c += wlin[h] * b2[h];
            d_c2 = c;
        }
    }
    int n = blockIdx.x * 256 + tid;
    if (n < N_NODES) d_deg[n] = 0;
}

// ---- dual GEMM (f32x2 outer product) + inlined degree count prologue -----
#define XPAD 68
#define WTPAD 132
#define SM_X_OFF 0
#define SM_WT_OFF (128 * XPAD)
#define SMEM_FLOATS (128 * XPAD + 64 * WTPAD)
#define GEMM_GRID 296

__global__ __launch_bounds__(256, 2)
void k_gemm(const float* __restrict__ x, const float* __restrict__ w1rel,
            const float* __restrict__ w1root, const float* __restrict__ b1,
            const int* __restrict__ ei) {
    extern __shared__ float sm[];
    float* sX  = sm + SM_X_OFF;    // [128][XPAD]
    float* sWt = sm + SM_WT_OFF;   // [64][WTPAD]

    int tid = threadIdx.x;

    // --- degree-count prologue: fire-and-forget RED atomics (hidden work) --
    {
        int gtid = blockIdx.x * 256 + tid;
        for (int e = gtid; e < N_EDGES; e += GEMM_GRID * 256)
            atomicAdd(&d_deg[ei[N_EDGES + e]], 1);
    }

    for (int idx = tid; idx < 128 * 64; idx += 256) {
        int o = idx >> 6, k = idx & 63;
        float v = (o < 64) ? w1rel[o * 64 + k] : w1root[(o - 64) * 64 + k];
        sWt[k * WTPAD + o] = v;
    }

    int tr = tid >> 4;
    int tc = tid & 15;
    int n0 = tr * 8;
    int o0 = tc * 8;
    float bb[8];
    #pragma unroll
    for (int q = 0; q < 8; q++) bb[q] = (tc >= 8) ? b1[o0 - 64 + q] : 0.f;

    const int ntiles = (N_NODES + 127) / 128;   // 782
    for (int tile = blockIdx.x; tile < ntiles; tile += gridDim.x) {
        int nbase  = tile * 128;
        int nvalid = min(128, N_NODES - nbase);
        __syncthreads();
        const float4* xg = reinterpret_cast<const float4*>(x + (size_t)nbase * F);
        #pragma unroll
        for (int i = 0; i < 8; i++) {
            int idx = tid + i * 256;
            int row = idx >> 4, c4 = idx & 15;
            float4 v = make_float4(0.f, 0.f, 0.f, 0.f);
            if (row < nvalid) v = xg[idx];
            *reinterpret_cast<float4*>(&sX[row * XPAD + c4 * 4]) = v;
        }
        __syncthreads();

        unsigned long long acc[8][4];
        #pragma unroll
        for (int n = 0; n < 8; n++)
            #pragma unroll
            for (int p = 0; p < 4; p++) acc[n][p] = 0ull;

        #pragma unroll 4
        for (int kk = 0; kk < 64; kk += 4) {
            unsigned long long b[4][4];
            #pragma unroll
            for (int j = 0; j < 4; j++) {
                ulonglong2 t0 = *reinterpret_cast<const ulonglong2*>(&sWt[(kk + j) * WTPAD + o0]);
                ulonglong2 t1 = *reinterpret_cast<const ulonglong2*>(&sWt[(kk + j) * WTPAD + o0 + 4]);
                b[j][0] = t0.x; b[j][1] = t0.y; b[j][2] = t1.x; b[j][3] = t1.y;
            }
            #pragma unroll
            for (int n = 0; n < 8; n++) {
                float4 av = *reinterpret_cast<const float4*>(&sX[(n0 + n) * XPAD + kk]);
                float as[4] = {av.x, av.y, av.z, av.w};
                #pragma unroll
                for (int j = 0; j < 4; j++) {
                    unsigned long long a2;
                    asm("mov.b64 %0, {%1, %1};" : "=l"(a2) : "f"(as[j]));
                    #pragma unroll
                    for (int p = 0; p < 4; p++)
                        asm("fma.rn.f32x2 %0, %1, %2, %3;"
                            : "=l"(acc[n][p])
                            : "l"(a2), "l"(b[j][p]), "l"(acc[n][p]));
                }
            }
        }

        #pragma unroll
        for (int n = 0; n < 8; n++) {
            int node = n0 + n;
            if (node >= nvalid) break;
            float o_[8];
            #pragma unroll
            for (int p = 0; p < 4; p++) {
                o_[2*p]   = __uint_as_float((unsigned)(acc[n][p] & 0xffffffffu));
                o_[2*p+1] = __uint_as_float((unsigned)(acc[n][p] >> 32));
            }
            size_t gbase = (size_t)(nbase + node) * F;
            if (tc < 8) {
                *reinterpret_cast<float4*>(&d_XR[gbase + o0]) =
                    make_float4(o_[0], o_[1], o_[2], o_[3]);
                *reinterpret_cast<float4*>(&d_XR[gbase + o0 + 4]) =
                    make_float4(o_[4], o_[5], o_[6], o_[7]);
            } else {
                *reinterpret_cast<float4*>(&d_H[gbase + o0 - 64]) =
                    make_float4(o_[0] + bb[0], o_[1] + bb[1], o_[2] + bb[2], o_[3] + bb[3]);
                *reinterpret_cast<float4*>(&d_H[gbase + o0 - 60]) =
                    make_float4(o_[4] + bb[4], o_[5] + bb[5], o_[6] + bb[6], o_[7] + bb[7]);
            }
        }
    }
}

// ---- fused exclusive scan: one block, 1024 threads, 98-node chunks -------
__global__ __launch_bounds__(1024)
void k_scan() {
    __shared__ int wsum[32];
    int tid = threadIdx.x;
    int beg = tid * CHUNK;
    int end = min(beg + CHUNK, N_NODES);
    int s = 0;
    for (int n = beg; n < end; n++) s += d_deg[n];

    int lane = tid & 31, wid = tid >> 5;
    int v = s;
    #pragma unroll
    for (int o = 1; o < 32; o <<= 1) {
        int t = __shfl_up_sync(0xffffffffu, v, o);
        if (lane >= o) v += t;
    }                                   // inclusive within warp
    if (lane == 31) wsum[wid] = v;
    __syncthreads();
    if (wid == 0) {
        int wv = wsum[lane];
        #pragma unroll
        for (int o = 1; o < 32; o <<= 1) {
            int t = __shfl_up_sync(0xffffffffu, wv, o);
            if (lane >= o) wv += t;
        }
        wsum[lane] = wv;                // inclusive warp totals
    }
    __syncthreads();
    int run = v - s + (wid > 0 ? wsum[wid - 1] : 0);   // thread-exclusive base
    for (int n = beg; n < end; n++) {
        int d = d_deg[n];
        d_off[n] = run;
        d_cursor[n] = run;
        run += d;
    }
}

__global__ __launch_bounds__(256)
void k_fill(const int* __restrict__ ei, const float* __restrict__ ew) {
    int e = blockIdx.x * blockDim.x + threadIdx.x;
    if (e >= N_EDGES) return;
    int src = ei[e];
    int dst = ei[N_EDGES + e];
    int slot = atomicAdd(&d_cursor[dst], 1);
    d_ep[slot] = make_int2(src, __float_as_int(ew[e]));
}

// ---- aggr: warp/node, float2 lanes, unroll-8 main + scalar tail (R9) -----
__global__ __launch_bounds__(256)
void k_aggr() {
    int node = (blockIdx.x * blockDim.x + threadIdx.x) >> 5;
    int l    = threadIdx.x & 31;
    if (node >= N_NODES) return;
    int beg = d_off[node];
    int end = beg + d_deg[node];
    float a0 = 0.f, a1 = 0.f;
    const float2* XR2 = reinterpret_cast<const float2*>(d_XR);
    int j = beg;
    for (; j + 8 <= end; j += 8) {
        int2 e[8];
        #pragma unroll
        for (int q = 0; q < 8; q++) e[q] = d_ep[j + q];
        float2 v[8];
        #pragma unroll
        for (int q = 0; q < 8; q++) v[q] = XR2[(size_t)e[q].x * 32 + l];
        #pragma unroll
        for (int q = 0; q < 8; q++) {
            float w = __int_as_float(e[q].y);
            a0 = fmaf(w, v[q].x, a0);
            a1 = fmaf(w, v[q].y, a1);
        }
    }
    for (; j < end; j++) {
        int2 e = d_ep[j];
        float2 v = XR2[(size_t)e.x * 32 + l];
        float w = __int_as_float(e.y);
        a0 = fmaf(w, v.x, a0);
        a1 = fmaf(w, v.y, a1);
    }
    float2 hh = reinterpret_cast<const float2*>(d_H)[(size_t)node * 32 + l];
    float h0 = fmaxf(hh.x + a0, 0.f);
    float h1 = fmaxf(hh.y + a1, 0.f);
    float2 vr = reinterpret_cast<const float2*>(d_vrel)[l];
    float2 vo = reinterpret_cast<const float2*>(d_vroot)[l];
    float pa = h0 * vr.x + h1 * vr.y;
    float ps = h0 * vo.x + h1 * vo.y;
    #pragma unroll
    for (int o = 16; o; o >>= 1) {
        pa += __shfl_xor_sync(0xffffffffu, pa, o);
        ps += __shfl_xor_sync(0xffffffffu, ps, o);
    }
    if (l == 0) { d_a[node] = pa; d_S[node] = ps + d_c2; }
}

// ---- layer2 scalar aggregation (unroll-4 + tail, R9) + pool bins ---------
__global__ __launch_bounds__(256)
void k_scalar_pool(const int* __restrict__ batch) {
    __shared__ float sb[G];
    __shared__ float sc[G];
    int tid = threadIdx.x;
    if (tid < G) { sb[tid] = 0.f; sc[tid] = 0.f; }
    __syncthreads();
    int n = blockIdx.x * blockDim.x + tid;
    if (n < N_NODES) {
        int beg = d_off[n];
        int end = beg + d_deg[n];
        float s = 0.f;
        int j = beg;
        for (; j + 4 <= end; j += 4) {
            int2 e0 = d_ep[j],     e1 = d_ep[j + 1];
            int2 e2 = d_ep[j + 2], e3 = d_ep[j + 3];
            float v0 = d_a[e0.x], v1 = d_a[e1.x];
            float v2 = d_a[e2.x], v3 = d_a[e3.x];
            s = fmaf(__int_as_float(e0.y), v0, s);
            s = fmaf(__int_as_float(e1.y), v1, s);
            s = fmaf(__int_as_float(e2.y), v2, s);
            s = fmaf(__int_as_float(e3.y), v3, s);
        }
        for (; j < end; j++) {
            int2 e = d_ep[j];
            s = fmaf(__int_as_float(e.y), d_a[e.x], s);
        }
        float S = d_S[n] + s;
        int b = batch[n];
        atomicAdd(&sb[b], S);
        atomicAdd(&sc[b], 1.0f);
    }
    __syncthreads();
    if (tid < G && (sb[tid] != 0.f || sc[tid] != 0.f)) {
        atomicAdd(&d_gsum[tid], sb[tid]);
        atomicAdd(&d_gcnt[tid], sc[tid]);
    }
}

// ---------------- final ----------------------------------------------------
__global__ void k_final(const float* __restrict__ blin, float* __restrict__ out) {
    int g = threadIdx.x;
    if (g < G) out[g] = d_gsum[g] / fmaxf(d_gcnt[g], 1.0f) + blin[0];
}

// ---------------- launch ---------------------------------------------------
extern "C" void kernel_launch(void* const* d_in, const int* in_sizes, int n_in,
                              void* d_out, int out_size) {
    const float* x     = (const float*)d_in[0];
    const int*   ei    = (const int*)d_in[1];      // int32 (JAX x64 disabled)
    const float* ew    = (const float*)d_in[2];
    const int*   batch = (const int*)d_in[3];
    const float* w1rel = (const float*)d_in[4];
    const float* b1rel = (const float*)d_in[5];
    const float* w1rt  = (const float*)d_in[6];
    const float* w2rel = (const float*)d_in[7];
    const float* b2rel = (const float*)d_in[8];
    const float* w2rt  = (const float*)d_in[9];
    const float* wlin  = (const float*)d_in[10];
    const float* blin  = (const float*)d_in[11];
    float* out = (float*)d_out;

    cudaFuncSetAttribute(k_gemm, cudaFuncAttributeMaxDynamicSharedMemorySize,
                         SMEM_FLOATS * 4);

    k_init_zero<<<(N_NODES + 255) / 256, 256>>>(w2rel, w2rt, b2rel, wlin);
    k_gemm<<<GEMM_GRID, 256, SMEM_FLOATS * 4>>>(x, w1rel, w1rt, b1rel, ei);
    k_scan<<<1, 1024>>>();
    k_fill<<<(N_EDGES + 255) / 256, 256>>>(ei, ew);
    k_aggr<<<(N_NODES * 32 + 255) / 256, 256>>>();
    k_scalar_pool<<<(N_NODES + 255) / 256, 256>>>(batch);
    k_final<<<1, 128>>>(blin, out);
}

// round 15
// speedup vs baseline: 2.0969x; 2.0150x over previous
#include <cuda_runtime.h>
#include <cstdint>

#define N_NODES 100000
#define N_EDGES 1000000
#define F 64
#define G 128
#define SCANB 1024
#define NSCAN ((N_NODES + SCANB - 1) / SCANB)   // 98

// ---------------- scratch (static device globals; no allocation) ----------
__device__ __align__(16) float d_XR[(size_t)N_NODES * F];  // x @ w1_rel.T
__device__ __align__(16) float d_H [(size_t)N_NODES * F];  // x @ w1_root.T + b1
__device__ float d_a [N_NODES];
__device__ float d_S [N_NODES];
__device__ __align__(8) float d_vrel[F];
__device__ __align__(8) float d_vroot[F];
__device__ float d_c2;
__device__ float d_gsum[G];
__device__ float d_gcnt[G];
// CSR by dst
__device__ int   d_deg[N_NODES];
__device__ int   d_off[N_NODES];
__device__ int   d_cursor[N_NODES];
__device__ int   d_part[128];
__device__ __align__(8) int2 d_ep[N_EDGES];   // {src, __float_as_int(w)}

// ------- init (block 0) + zero degree histogram (all blocks) --------------
__global__ __launch_bounds__(256)
void k_init_zero(const float* __restrict__ w2rel,
                 const float* __restrict__ w2root,
                 const float* __restrict__ b2,
                 const float* __restrict__ wlin) {
    int tid = threadIdx.x;
    if (blockIdx.x == 0) {
        if (tid < G) { d_gsum[tid] = 0.f; d_gcnt[tid] = 0.f; }
        if (tid < F) {
            float vr = 0.f, vo = 0.f;
            #pragma unroll 8
            for (int h = 0; h < F; h++) {
                float wl = wlin[h];
                vr += wl * w2rel[h * F + tid];
                vo += wl * w2root[h * F + tid];
            }
            d_vrel[tid] = vr; d_vroot[tid] = vo;
        }
        if (tid == 0) {
            float c = 0.f;
            for (int h = 0; h < F; h++) c += wlin[h] * b2[h];
            d_c2 = c;
        }
    }
    int n = blockIdx.x * 256 + tid;
    if (n < N_NODES) d_deg[n] = 0;
}

// ---- dual GEMM (f32x2 outer product) + inlined degree count prologue -----
#define XPAD 68
#define WTPAD 132
#define SM_X_OFF 0
#define SM_WT_OFF (128 * XPAD)
#define SMEM_FLOATS (128 * XPAD + 64 * WTPAD)
#define GEMM_GRID 296

__global__ __launch_bounds__(256, 2)
void k_gemm(const float* __restrict__ x, const float* __restrict__ w1rel,
            const float* __restrict__ w1root, const float* __restrict__ b1,
            const int* __restrict__ ei) {
    extern __shared__ float sm[];
    float* sX  = sm + SM_X_OFF;    // [128][XPAD]
    float* sWt = sm + SM_WT_OFF;   // [64][WTPAD]

    int tid = threadIdx.x;

    // --- degree-count prologue: fire-and-forget RED atomics (hidden work) --
    {
        int gtid = blockIdx.x * 256 + tid;
        for (int e = gtid; e < N_EDGES; e += GEMM_GRID * 256)
            atomicAdd(&d_deg[ei[N_EDGES + e]], 1);
    }

    for (int idx = tid; idx < 128 * 64; idx += 256) {
        int o = idx >> 6, k = idx & 63;
        float v = (o < 64) ? w1rel[o * 64 + k] : w1root[(o - 64) * 64 + k];
        sWt[k * WTPAD + o] = v;
    }

    int tr = tid >> 4;
    int tc = tid & 15;
    int n0 = tr * 8;
    int o0 = tc * 8;
    float bb[8];
    #pragma unroll
    for (int q = 0; q < 8; q++) bb[q] = (tc >= 8) ? b1[o0 - 64 + q] : 0.f;

    const int ntiles = (N_NODES + 127) / 128;   // 782
    for (int tile = blockIdx.x; tile < ntiles; tile += gridDim.x) {
        int nbase  = tile * 128;
        int nvalid = min(128, N_NODES - nbase);
        __syncthreads();
        const float4* xg = reinterpret_cast<const float4*>(x + (size_t)nbase * F);
        #pragma unroll
        for (int i = 0; i < 8; i++) {
            int idx = tid + i * 256;
            int row = idx >> 4, c4 = idx & 15;
            float4 v = make_float4(0.f, 0.f, 0.f, 0.f);
            if (row < nvalid) v = xg[idx];
            *reinterpret_cast<float4*>(&sX[row * XPAD + c4 * 4]) = v;
        }
        __syncthreads();

        unsigned long long acc[8][4];
        #pragma unroll
        for (int n = 0; n < 8; n++)
            #pragma unroll
            for (int p = 0; p < 4; p++) acc[n][p] = 0ull;

        #pragma unroll 4
        for (int kk = 0; kk < 64; kk += 4) {
            unsigned long long b[4][4];
            #pragma unroll
            for (int j = 0; j < 4; j++) {
                ulonglong2 t0 = *reinterpret_cast<const ulonglong2*>(&sWt[(kk + j) * WTPAD + o0]);
                ulonglong2 t1 = *reinterpret_cast<const ulonglong2*>(&sWt[(kk + j) * WTPAD + o0 + 4]);
                b[j][0] = t0.x; b[j][1] = t0.y; b[j][2] = t1.x; b[j][3] = t1.y;
            }
            #pragma unroll
            for (int n = 0; n < 8; n++) {
                float4 av = *reinterpret_cast<const float4*>(&sX[(n0 + n) * XPAD + kk]);
                float as[4] = {av.x, av.y, av.z, av.w};
                #pragma unroll
                for (int j = 0; j < 4; j++) {
                    unsigned long long a2;
                    asm("mov.b64 %0, {%1, %1};" : "=l"(a2) : "f"(as[j]));
                    #pragma unroll
                    for (int p = 0; p < 4; p++)
                        asm("fma.rn.f32x2 %0, %1, %2, %3;"
                            : "=l"(acc[n][p])
                            : "l"(a2), "l"(b[j][p]), "l"(acc[n][p]));
                }
            }
        }

        #pragma unroll
        for (int n = 0; n < 8; n++) {
            int node = n0 + n;
            if (node >= nvalid) break;
            float o_[8];
            #pragma unroll
            for (int p = 0; p < 4; p++) {
                o_[2*p]   = __uint_as_float((unsigned)(acc[n][p] & 0xffffffffu));
                o_[2*p+1] = __uint_as_float((unsigned)(acc[n][p] >> 32));
            }
            size_t gbase = (size_t)(nbase + node) * F;
            if (tc < 8) {
                *reinterpret_cast<float4*>(&d_XR[gbase + o0]) =
                    make_float4(o_[0], o_[1], o_[2], o_[3]);
                *reinterpret_cast<float4*>(&d_XR[gbase + o0 + 4]) =
                    make_float4(o_[4], o_[5], o_[6], o_[7]);
            } else {
                *reinterpret_cast<float4*>(&d_H[gbase + o0 - 64]) =
                    make_float4(o_[0] + bb[0], o_[1] + bb[1], o_[2] + bb[2], o_[3] + bb[3]);
                *reinterpret_cast<float4*>(&d_H[gbase + o0 - 60]) =
                    make_float4(o_[4] + bb[4], o_[5] + bb[5], o_[6] + bb[6], o_[7] + bb[7]);
            }
        }
    }
}

// ---------------- CSR scans (R9 structure; scanB parallelized) ------------
__global__ void k_scanA() {
    __shared__ int s[SCANB];
    int tid = threadIdx.x;
    int n = blockIdx.x * SCANB + tid;
    s[tid] = (n < N_NODES) ? d_deg[n] : 0;
    __syncthreads();
    for (int o = SCANB / 2; o; o >>= 1) {
        if (tid < o) s[tid] += s[tid + o];
        __syncthreads();
    }
    if (tid == 0) d_part[blockIdx.x] = s[0];
}

// parallel exclusive scan of NSCAN=98 partials (128 threads, shfl + smem)
__global__ void k_scanB() {
    __shared__ int wtot[4];
    int tid  = threadIdx.x;           // 0..127
    int lane = tid & 31, wid = tid >> 5;
    int v = (tid < NSCAN) ? d_part[tid] : 0;
    int inc = v;
    #pragma unroll
    for (int o = 1; o < 32; o <<= 1) {
        int t = __shfl_up_sync(0xffffffffu, inc, o);
        if (lane >= o) inc += t;
    }
    if (lane == 31) wtot[wid] = inc;
    __syncthreads();
    int base = 0;
    #pragma unroll
    for (int w = 0; w < 4; w++) if (w < wid) base += wtot[w];
    if (tid < NSCAN) d_part[tid] = base + inc - v;   // exclusive
}

__global__ void k_scanC() {
    __shared__ int s[SCANB];
    int tid = threadIdx.x;
    int n = blockIdx.x * SCANB + tid;
    int v = (n < N_NODES) ? d_deg[n] : 0;
    s[tid] = v;
    __syncthreads();
    for (int o = 1; o < SCANB; o <<= 1) {
        int t = (tid >= o) ? s[tid - o] : 0;
        __syncthreads();
        s[tid] += t;
        __syncthreads();
    }
    if (n < N_NODES) {
        int off = d_part[blockIdx.x] + s[tid] - v;
        d_off[n] = off;
        d_cursor[n] = off;
    }
}

__global__ __launch_bounds__(256)
void k_fill(const int* __restrict__ ei, const float* __restrict__ ew) {
    int e = blockIdx.x * blockDim.x + threadIdx.x;
    if (e >= N_EDGES) return;
    int src = ei[e];
    int dst = ei[N_EDGES + e];
    int slot = atomicAdd(&d_cursor[dst], 1);
    d_ep[slot] = make_int2(src, __float_as_int(ew[e]));
}

// ---- aggr: warp/node, float2 lanes, unroll-8 main + scalar tail ----------
__global__ __launch_bounds__(256)
void k_aggr() {
    int node = (blockIdx.x * blockDim.x + threadIdx.x) >> 5;
    int l    = threadIdx.x & 31;
    if (node >= N_NODES) return;
    int beg = d_off[node];
    int end = beg + d_deg[node];
    float a0 = 0.f, a1 = 0.f;
    const float2* XR2 = reinterpret_cast<const float2*>(d_XR);
    int j = beg;
    for (; j + 8 <= end; j += 8) {
        int2 e[8];
        #pragma unroll
        for (int q = 0; q < 8; q++) e[q] = d_ep[j + q];
        float2 v[8];
        #pragma unroll
        for (int q = 0; q < 8; q++) v[q] = XR2[(size_t)e[q].x * 32 + l];
        #pragma unroll
        for (int q = 0; q < 8; q++) {
            float w = __int_as_float(e[q].y);
            a0 = fmaf(w, v[q].x, a0);
            a1 = fmaf(w, v[q].y, a1);
        }
    }
    for (; j < end; j++) {
        int2 e = d_ep[j];
        float2 v = XR2[(size_t)e.x * 32 + l];
        float w = __int_as_float(e.y);
        a0 = fmaf(w, v.x, a0);
        a1 = fmaf(w, v.y, a1);
    }
    float2 hh = reinterpret_cast<const float2*>(d_H)[(size_t)node * 32 + l];
    float h0 = fmaxf(hh.x + a0, 0.f);
    float h1 = fmaxf(hh.y + a1, 0.f);
    float2 vr = reinterpret_cast<const float2*>(d_vrel)[l];
    float2 vo = reinterpret_cast<const float2*>(d_vroot)[l];
    float pa = h0 * vr.x + h1 * vr.y;
    float ps = h0 * vo.x + h1 * vo.y;
    #pragma unroll
    for (int o = 16; o; o >>= 1) {
        pa += __shfl_xor_sync(0xffffffffu, pa, o);
        ps += __shfl_xor_sync(0xffffffffu, ps, o);
    }
    if (l == 0) { d_a[node] = pa; d_S[node] = ps + d_c2; }
}

// ---- layer2 scalar aggregation (unroll-4 + tail) + pool bins -------------
__global__ __launch_bounds__(256)
void k_scalar_pool(const int* __restrict__ batch) {
    __shared__ float sb[G];
    __shared__ float sc[G];
    int tid = threadIdx.x;
    if (tid < G) { sb[tid] = 0.f; sc[tid] = 0.f; }
    __syncthreads();
    int n = blockIdx.x * blockDim.x + tid;
    if (n < N_NODES) {
        int beg = d_off[n];
        int end = beg + d_deg[n];
        float s = 0.f;
        int j = beg;
        for (; j + 4 <= end; j += 4) {
            int2 e0 = d_ep[j],     e1 = d_ep[j + 1];
            int2 e2 = d_ep[j + 2], e3 = d_ep[j + 3];
            float v0 = d_a[e0.x], v1 = d_a[e1.x];
            float v2 = d_a[e2.x], v3 = d_a[e3.x];
            s = fmaf(__int_as_float(e0.y), v0, s);
            s = fmaf(__int_as_float(e1.y), v1, s);
            s = fmaf(__int_as_float(e2.y), v2, s);
            s = fmaf(__int_as_float(e3.y), v3, s);
        }
        for (; j < end; j++) {
            int2 e = d_ep[j];
            s = fmaf(__int_as_float(e.y), d_a[e.x], s);
        }
        float S = d_S[n] + s;
        int b = batch[n];
        atomicAdd(&sb[b], S);
        atomicAdd(&sc[b], 1.0f);
    }
    __syncthreads();
    if (tid < G && (sb[tid] != 0.f || sc[tid] != 0.f)) {
        atomicAdd(&d_gsum[tid], sb[tid]);
        atomicAdd(&d_gcnt[tid], sc[tid]);
    }
}

// ---------------- final ----------------------------------------------------
__global__ void k_final(const float* __restrict__ blin, float* __restrict__ out) {
    int g = threadIdx.x;
    if (g < G) out[g] = d_gsum[g] / fmaxf(d_gcnt[g], 1.0f) + blin[0];
}

// ---------------- launch ---------------------------------------------------
extern "C" void kernel_launch(void* const* d_in, const int* in_sizes, int n_in,
                              void* d_out, int out_size) {
    const float* x     = (const float*)d_in[0];
    const int*   ei    = (const int*)d_in[1];      // int32 (JAX x64 disabled)
    const float* ew    = (const float*)d_in[2];
    const int*   batch = (const int*)d_in[3];
    const float* w1rel = (const float*)d_in[4];
    const float* b1rel = (const float*)d_in[5];
    const float* w1rt  = (const float*)d_in[6];
    const float* w2rel = (const float*)d_in[7];
    const float* b2rel = (const float*)d_in[8];
    const float* w2rt  = (const float*)d_in[9];
    const float* wlin  = (const float*)d_in[10];
    const float* blin  = (const float*)d_in[11];
    float* out = (float*)d_out;

    cudaFuncSetAttribute(k_gemm, cudaFuncAttributeMaxDynamicSharedMemorySize,
                         SMEM_FLOATS * 4);

    k_init_zero<<<(N_NODES + 255) / 256, 256>>>(w2rel, w2rt, b2rel, wlin);
    k_gemm<<<GEMM_GRID, 256, SMEM_FLOATS * 4>>>(x, w1rel, w1rt, b1rel, ei);
    k_scanA<<<NSCAN, SCANB>>>();
    k_scanB<<<1, 128>>>();
    k_scanC<<<NSCAN, SCANB>>>();
    k_fill<<<(N_EDGES + 255) / 256, 256>>>(ei, ew);
    k_aggr<<<(N_NODES * 32 + 255) / 256, 256>>>();
    k_scalar_pool<<<(N_NODES + 255) / 256, 256>>>(batch);
    k_final<<<1, 128>>>(blin, out);
}